// round 6
// baseline (speedup 1.0000x reference)
#include <cuda_runtime.h>
#include <cstdint>

// ---------------------------------------------------------------------------
// Fused 2-layer LSTM, S=4096, B=64, I=14, H=256, O=1 (gate order i,f,g,o)
//
// 8 batch groups x 16 CTAs; each CTA: weight replica slice in smem,
// 16 hidden units x 8 batch elems, BOTH layers. NT=512.
// Thread = (kq, jl, b):
//   all kq: layer0 k-quarter (32 kp)
//   kq0/kq1: layer1 Wih1 k-half;  kq2/kq3: layer1 Whh1 k-half
//   kq3 folds x[t] into its layer0 partial and stages x[t+1]
//   kq0 finalizes layer0; kq1 finalizes layer1 + FC
// Sync per step: producers (kq0+kq1) bar.sync -> red.release ->
// ALL threads pure-spin on group flag -> each warp issues its own cp.async
// (no wake-up syncthreads, no nanosleep).
// ---------------------------------------------------------------------------

#define S_LEN  4096
#define BATCH  64
#define IN0    14
#define HID    256
#define NB     128
#define NT     512
#define NGRP   8
#define GCTAS  16
#define JL     16
#define BG     8
#define HBUF   (HID*BG)

// ---- global scratch --------------------------------------------------------
__device__ float    g_h0x[NGRP][2][HBUF];   // [(kp*8+b)*2 + (k&1)]
__device__ float    g_h1x[NGRP][2][HBUF];
__device__ unsigned g_barG[NGRP * 32];

// ---- packed fp32x2 helpers -------------------------------------------------
__device__ __forceinline__ unsigned long long pack2(float x, float y) {
    unsigned long long r;
    asm("mov.b64 %0, {%1,%2};" : "=l"(r) : "f"(x), "f"(y));
    return r;
}
__device__ __forceinline__ void unpack2(unsigned long long v, float& x, float& y) {
    asm("mov.b64 {%0,%1}, %2;" : "=f"(x), "=f"(y) : "l"(v));
}
__device__ __forceinline__ unsigned long long ffma2(unsigned long long a,
                                                    unsigned long long b,
                                                    unsigned long long c) {
    unsigned long long d;
    asm("fma.rn.f32x2 %0, %1, %2, %3;" : "=l"(d) : "l"(a), "l"(b), "l"(c));
    return d;
}
__device__ __forceinline__ float sum2(unsigned long long v) {
    float lo, hi; unpack2(v, lo, hi); return lo + hi;
}

// ---- activations -----------------------------------------------------------
__device__ __forceinline__ float sigmoidf_(float v) {
    return 1.0f / (1.0f + __expf(-v));
}
__device__ __forceinline__ float tanh_acc(float v) {
    float a = fabsf(v);
    float e = __expf(-2.0f * a);
    float r = __fdividef(1.0f - e, 1.0f + e);
    return v < 0.0f ? -r : r;
}

// ---- sync primitives -------------------------------------------------------
__device__ __forceinline__ void red_rel_add(unsigned* p) {
    asm volatile("red.release.gpu.global.add.u32 [%0], %1;" :: "l"(p), "r"(1u) : "memory");
}
__device__ __forceinline__ unsigned ld_acq(const unsigned* p) {
    unsigned v;
    asm volatile("ld.acquire.gpu.global.u32 %0, [%1];" : "=r"(v) : "l"(p) : "memory");
    return v;
}
__device__ __forceinline__ void cp16(uint32_t dst, const void* src) {
    asm volatile("cp.async.cg.shared.global [%0], [%1], 16;" :: "r"(dst), "l"(src));
}
__device__ __forceinline__ void mbar_init(uint32_t a, uint32_t cnt) {
    asm volatile("mbarrier.init.shared.b64 [%0], %1;" :: "r"(a), "r"(cnt) : "memory");
}
__device__ __forceinline__ void cp_arrive_noinc(uint32_t a) {
    asm volatile("cp.async.mbarrier.arrive.noinc.shared.b64 [%0];" :: "r"(a) : "memory");
}
__device__ __forceinline__ void mbar_wait_parity(uint32_t addr, uint32_t parity) {
    asm volatile(
        "{\n\t.reg .pred P;\n"
        "MW_%=:\n\t"
        "mbarrier.try_wait.parity.shared::cta.b64 P, [%0], %1;\n\t"
        "@!P bra MW_%=;\n\t}"
        :: "r"(addr), "r"(parity) : "memory");
}
__device__ __forceinline__ float warp_reduce(float p) {
    #pragma unroll
    for (int o = 16; o > 0; o >>= 1) p += __shfl_xor_sync(0xffffffffu, p, o);
    return p;
}

// ---- smem layout (bytes) ---------------------------------------------------
#define SH_W0    0          // 65536  Whh0   ull slot (kp*16+jl)*4+gate
#define SH_WI1   65536      // 65536  Wih1
#define SH_WH1   131072     // 65536  Whh1
#define SH_WI0   196608     // 3584   float4 wi0[16][14]
#define SH_H0    200192     // 8192   ull[kp128][b8]
#define SH_H1    208384     // 8192
#define SH_PL0   216576     // 6144   float4[3][128]
#define SH_PL1   222720     // 6144   float4[3][128]
#define SH_X     228864     // 896    float[2][112]
#define SH_RED   229760     // 32
#define SH_MBAR  229792     // 16
#define SMEM_TOTAL 229808

extern "C" __global__ void __launch_bounds__(NT, 1)
lstm_fused(const float* __restrict__ x,   const float* __restrict__ c0,
           const float* __restrict__ Wih0, const float* __restrict__ Whh0,
           const float* __restrict__ bih0, const float* __restrict__ bhh0,
           const float* __restrict__ Wih1, const float* __restrict__ Whh1,
           const float* __restrict__ bih1, const float* __restrict__ bhh1,
           const float* __restrict__ Wfc,  const float* __restrict__ bfc,
           float* __restrict__ out)
{
    extern __shared__ char smem[];
    unsigned long long* w0u    = (unsigned long long*)(smem + SH_W0);
    unsigned long long* wi1u   = (unsigned long long*)(smem + SH_WI1);
    unsigned long long* wh1u   = (unsigned long long*)(smem + SH_WH1);
    float4*             wi0    = (float4*)(smem + SH_WI0);
    unsigned long long* sh_h0u = (unsigned long long*)(smem + SH_H0);
    unsigned long long* sh_h1u = (unsigned long long*)(smem + SH_H1);
    float*              sh_h1f = (float*)(smem + SH_H1);
    float4*             pl0    = (float4*)(smem + SH_PL0);
    float4*             pl1    = (float4*)(smem + SH_PL1);
    float*              shx    = (float*)(smem + SH_X);
    float*              red4   = (float*)(smem + SH_RED);

    const uint32_t smem_h0 = (uint32_t)__cvta_generic_to_shared(smem + SH_H0);
    const uint32_t smem_h1 = (uint32_t)__cvta_generic_to_shared(smem + SH_H1);
    const uint32_t mb0     = (uint32_t)__cvta_generic_to_shared(smem + SH_MBAR);
    const uint32_t mb1     = mb0 + 8;

    const int tid = threadIdx.x;
    const int bid = blockIdx.x;
    const int gid = bid >> 4;
    const int ci  = bid & 15;
    const int kq  = tid >> 7;           // 0..3
    const int f   = tid & 127;
    const int jl  = f >> 3;
    const int b   = f & 7;
    const int jglob = ci * JL + jl;

    if (tid == 0) { mbar_init(mb0, NT); mbar_init(mb1, NT); }

    // ---- preload weight slices --------------------------------------------
    for (int e = tid; e < 128 * 16 * 4; e += NT) {
        int kp = e & 127;
        int r  = e >> 7;
        int wjl = r >> 2, gsel = r & 3;
        int row = (gsel * HID + ci * JL + wjl) * HID + 2 * kp;
        int slot = (kp * 16 + wjl) * 4 + gsel;
        w0u [slot] = pack2(Whh0[row], Whh0[row + 1]);
        wi1u[slot] = pack2(Wih1[row], Wih1[row + 1]);
        wh1u[slot] = pack2(Whh1[row], Whh1[row + 1]);
    }
    for (int e = tid; e < JL * IN0; e += NT) {
        int wjl = e / IN0, d = e % IN0;
        int jg = ci * JL + wjl;
        wi0[wjl * IN0 + d] = make_float4(
            Wih0[(0*HID + jg)*IN0 + d], Wih0[(1*HID + jg)*IN0 + d],
            Wih0[(2*HID + jg)*IN0 + d], Wih0[(3*HID + jg)*IN0 + d]);
    }

    // ---- per-role state ----------------------------------------------------
    const int bglob = gid * BG + b;
    float bs0 = 0.f, bs1 = 0.f, bs2 = 0.f, bs3 = 0.f, cst = 0.f;
    if (kq == 0) {
        bs0 = bih0[0*HID+jglob] + bhh0[0*HID+jglob];
        bs1 = bih0[1*HID+jglob] + bhh0[1*HID+jglob];
        bs2 = bih0[2*HID+jglob] + bhh0[2*HID+jglob];
        bs3 = bih0[3*HID+jglob] + bhh0[3*HID+jglob];
        cst = c0[bglob*HID + jglob];
    } else if (kq == 1) {
        bs0 = bih1[0*HID+jglob] + bhh1[0*HID+jglob];
        bs1 = bih1[1*HID+jglob] + bhh1[1*HID+jglob];
        bs2 = bih1[2*HID+jglob] + bhh1[2*HID+jglob];
        bs3 = bih1[3*HID+jglob] + bhh1[3*HID+jglob];
        cst = c0[(BATCH + bglob)*HID + jglob];
    }
    const float wfcA = Wfc[f];
    const float wfcB = Wfc[f + 128];
    const float bfc0 = bfc[0];

    for (int e = tid; e < BG*IN0; e += NT)
        shx[e] = x[(size_t)gid*BG*IN0 + e];
    __syncthreads();

    unsigned* bar = &g_barG[gid * 32];
    const int storeIdx = ((ci*8 + (jl>>1))*8 + b)*2 + (jl&1);

    // ---- prologue: prime cp.async for t=0 (parity 0) -----------------------
    {
        const float4* s0 = (const float4*)g_h0x[gid][0];
        const float4* s1 = (const float4*)g_h1x[gid][0];
        cp16(smem_h0 + tid*16, s0 + tid);
        cp_arrive_noinc(mb0);
        cp16(smem_h1 + tid*16, s1 + tid);
        cp_arrive_noinc(mb1);
    }

    for (int t = 0; t <= S_LEN; ++t) {
        const uint32_t par = (uint32_t)(t & 1);

        mbar_wait_parity(mb0, par);

        // ---- layer0 k-quarter (all roles) ----------------------------------
        unsigned long long a0=0,a1=0,a2=0,a3=0;
        if (t < S_LEN) {
            const unsigned long long* hp = sh_h0u + kq*32*8 + b;
            const unsigned long long* wq = w0u + kq*32*64 + jl*4;
            #pragma unroll 8
            for (int kp = 0; kp < 32; ++kp) {
                unsigned long long hv = hp[kp*8];
                const unsigned long long* w = wq + kp*64;
                ulonglong2 wA = *(const ulonglong2*)(w);
                ulonglong2 wB = *(const ulonglong2*)(w + 2);
                a0 = ffma2(hv, wA.x, a0); a1 = ffma2(hv, wA.y, a1);
                a2 = ffma2(hv, wB.x, a2); a3 = ffma2(hv, wB.y, a3);
            }
        }
        float l0x = sum2(a0), l0y = sum2(a1), l0z = sum2(a2), l0w = sum2(a3);

        // kq3: fold x[t] contribution; stage x[t+1] (ordered by combine sync)
        if (kq == 3) {
            if (t < S_LEN) {
                const float*  xr = shx + (t & 1)*(BG*IN0) + b*IN0;
                const float4* wi = wi0 + jl*IN0;
                #pragma unroll
                for (int d = 0; d < IN0; ++d) {
                    float xv = xr[d]; float4 w = wi[d];
                    l0x = fmaf(xv, w.x, l0x); l0y = fmaf(xv, w.y, l0y);
                    l0z = fmaf(xv, w.z, l0z); l0w = fmaf(xv, w.w, l0w);
                }
            }
            if (t + 1 < S_LEN && f < BG*IN0)
                shx[((t+1)&1)*(BG*IN0) + f] =
                    x[((size_t)(t+1)*BATCH + gid*BG)*IN0 + f];
        }
        if (kq != 0) pl0[(kq-1)*128 + f] = make_float4(l0x, l0y, l0z, l0w);

        // ---- layer1 half-GEMMs ---------------------------------------------
        unsigned long long e0=0,e1=0,e2=0,e3=0;
        if (kq < 2) {
            if (t >= 1) {                       // Wih1 x h0[t-1], half kq
                const unsigned long long* hp = sh_h0u + kq*64*8 + b;
                const unsigned long long* wq = wi1u + kq*64*64 + jl*4;
                #pragma unroll 8
                for (int kp = 0; kp < 64; ++kp) {
                    unsigned long long hv = hp[kp*8];
                    const unsigned long long* w = wq + kp*64;
                    ulonglong2 wA = *(const ulonglong2*)(w);
                    ulonglong2 wB = *(const ulonglong2*)(w + 2);
                    e0 = ffma2(hv, wA.x, e0); e1 = ffma2(hv, wA.y, e1);
                    e2 = ffma2(hv, wB.x, e2); e3 = ffma2(hv, wB.y, e3);
                }
            }
            if (kq == 0)
                pl1[f] = make_float4(sum2(e0), sum2(e1), sum2(e2), sum2(e3));
            else if (t >= 2) {
                // ---- fused FC for out[t-2]: reads sh_h1 (pre-combine, safe:
                // sh_h1 is only overwritten after every thread passes the
                // post-spin cp.async, which is after the combine sync) -------
                mbar_wait_parity(mb1, par);
                if (ci < BG) {
                    int j1 = f, j2 = f + 128;
                    float vA = sh_h1f[(j1>>1)*16 + ci*2 + (j1&1)];
                    float vB = sh_h1f[(j2>>1)*16 + ci*2 + (j2&1)];
                    float p = fmaxf(vA, 0.f)*wfcA + fmaxf(vB, 0.f)*wfcB;
                    p = warp_reduce(p);
                    if ((f & 31) == 0) red4[f >> 5] = p;
                    asm volatile("bar.sync 2, 128;" ::: "memory");
                    if (f == 0)
                        out[(size_t)(t-2)*BATCH + gid*BG + ci] =
                            red4[0]+red4[1]+red4[2]+red4[3] + bfc0;
                }
            }
        } else {
            mbar_wait_parity(mb1, par);
            if (t >= 1) {                       // Whh1 x h1[t-2], half kq-2
                const int kh = kq - 2;
                const unsigned long long* hp = sh_h1u + kh*64*8 + b;
                const unsigned long long* wq = wh1u + kh*64*64 + jl*4;
                #pragma unroll 8
                for (int kp = 0; kp < 64; ++kp) {
                    unsigned long long hv = hp[kp*8];
                    const unsigned long long* w = wq + kp*64;
                    ulonglong2 wA = *(const ulonglong2*)(w);
                    ulonglong2 wB = *(const ulonglong2*)(w + 2);
                    e0 = ffma2(hv, wA.x, e0); e1 = ffma2(hv, wA.y, e1);
                    e2 = ffma2(hv, wB.x, e2); e3 = ffma2(hv, wB.y, e3);
                }
            }
            pl1[(kq-1)*128 + f] = make_float4(sum2(e0), sum2(e1), sum2(e2), sum2(e3));
        }

        // ---- combine sync: also marks "all reads of sh_h0/sh_h1 done" ------
        __syncthreads();

        if (kq == 0) {
            if (t < S_LEN) {                    // finalize layer0 -> h0[t]
                float4 p1 = pl0[f], p2 = pl0[128+f], p3 = pl0[256+f];
                float gi = l0x + p1.x + p2.x + p3.x + bs0;
                float gf = l0y + p1.y + p2.y + p3.y + bs1;
                float gg = l0z + p1.z + p2.z + p3.z + bs2;
                float go = l0w + p1.w + p2.w + p3.w + bs3;
                gi = sigmoidf_(gi); gf = sigmoidf_(gf);
                gg = tanh_acc(gg);  go = sigmoidf_(go);
                cst = gf*cst + gi*gg;
                float h = go * tanh_acc(cst);
                g_h0x[gid][(t+1)&1][storeIdx] = h;
            }
        } else if (kq == 1) {
            if (t >= 1) {                       // finalize layer1 -> h1[t-1]
                float4 p1 = pl1[f], p2 = pl1[128+f], p3 = pl1[256+f];
                float gi = sum2(e0) + p1.x + p2.x + p3.x + bs0;
                float gf = sum2(e1) + p1.y + p2.y + p3.y + bs1;
                float gg = sum2(e2) + p1.z + p2.z + p3.z + bs2;
                float go = sum2(e3) + p1.w + p2.w + p3.w + bs3;
                gi = sigmoidf_(gi); gf = sigmoidf_(gf);
                gg = tanh_acc(gg);  go = sigmoidf_(go);
                cst = gf*cst + gi*gg;
                float h = go * tanh_acc(cst);
                g_h1x[gid][(t+1)&1][storeIdx] = h;
            }
        }

        if (t < S_LEN) {
            // ---- producer barrier + release (kq0+kq1 = threads 0..255) -----
            if (kq < 2) {
                asm volatile("bar.sync 3, 256;" ::: "memory");
                if (tid == 0) red_rel_add(bar);
            }
            // ---- all threads: pure spin, then issue own cp.async slice -----
            const unsigned target = (unsigned)GCTAS * (unsigned)(t + 1);
            while (ld_acq(bar) < target) { }
            const int npar = (t + 1) & 1;
            const float4* s0 = (const float4*)g_h0x[gid][npar];
            const float4* s1 = (const float4*)g_h1x[gid][npar];
            cp16(smem_h0 + tid*16, s0 + tid);
            cp_arrive_noinc(mb0);
            cp16(smem_h1 + tid*16, s1 + tid);
            cp_arrive_noinc(mb1);
        }
    }

    // ---- final FC row 4095: h1[4095] in g_h1x[gid][1] ----------------------
    if (kq == 1 && ci < BG) {
        int j1 = f, j2 = f + 128;
        float vA = __ldcg(&g_h1x[gid][1][(j1>>1)*16 + ci*2 + (j1&1)]);
        float vB = __ldcg(&g_h1x[gid][1][(j2>>1)*16 + ci*2 + (j2&1)]);
        float p = fmaxf(vA, 0.f)*wfcA + fmaxf(vB, 0.f)*wfcB;
        p = warp_reduce(p);
        if ((f & 31) == 0) red4[f >> 5] = p;
        asm volatile("bar.sync 2, 128;" ::: "memory");
        if (f == 0)
            out[(size_t)(S_LEN-1)*BATCH + gid*BG + ci] =
                red4[0]+red4[1]+red4[2]+red4[3] + bfc0;
    }
}

// ---------------------------------------------------------------------------
// Init: reset group barriers; scatter h0 init into exchange buffers.
// ---------------------------------------------------------------------------
extern "C" __global__ void lstm_init(const float* __restrict__ h0)
{
    int i = blockIdx.x * blockDim.x + threadIdx.x;
    if (i < NGRP * 32) g_barG[i] = 0u;
    for (int idx = i; idx < 2 * NGRP * HBUF; idx += gridDim.x * blockDim.x) {
        int l = idx >> 14;
        int rest = idx & 16383;
        int g = rest >> 11;
        int q = rest & 2047;
        int kp = q >> 4;
        int b  = (q >> 1) & 7;
        int par = q & 1;
        int k = kp*2 + par;
        float v = h0[(l*BATCH + g*BG + b)*HID + k];
        if (l == 0) g_h0x[g][0][q] = v;
        else        g_h1x[g][1][q] = v;
    }
}

// ---------------------------------------------------------------------------
extern "C" void kernel_launch(void* const* d_in, const int* in_sizes, int n_in,
                              void* d_out, int out_size)
{
    const float* x    = (const float*)d_in[0];
    const float* h0   = (const float*)d_in[1];
    const float* c0   = (const float*)d_in[2];
    const float* Wih0 = (const float*)d_in[3];
    const float* Whh0 = (const float*)d_in[4];
    const float* bih0 = (const float*)d_in[5];
    const float* bhh0 = (const float*)d_in[6];
    const float* Wih1 = (const float*)d_in[7];
    const float* Whh1 = (const float*)d_in[8];
    const float* bih1 = (const float*)d_in[9];
    const float* bhh1 = (const float*)d_in[10];
    const float* Wfc  = (const float*)d_in[11];
    const float* bfc  = (const float*)d_in[12];
    float* out = (float*)d_out;

    cudaFuncSetAttribute(lstm_fused, cudaFuncAttributeMaxDynamicSharedMemorySize, SMEM_TOTAL);

    lstm_init<<<64, 256>>>(h0);
    lstm_fused<<<NB, NT, SMEM_TOTAL>>>(x, c0, Wih0, Whh0, bih0, bhh0,
                                       Wih1, Whh1, bih1, bhh1, Wfc, bfc, out);
}

// round 7
// speedup vs baseline: 1.5836x; 1.5836x over previous
#include <cuda_runtime.h>
#include <cstdint>

// ---------------------------------------------------------------------------
// Fused 2-layer LSTM, S=4096, B=64, I=14, H=256, O=1 (gate order i,f,g,o)
//
// 8 batch groups x 16 CTAs; each CTA: weight replica slice in smem,
// 16 hidden units x 8 batch elems, BOTH layers. NT=512.
// Thread = (kq, jl, b):
//   all kq: layer0 k-quarter (32 kp)
//   kq0/kq1: layer1 Wih1 k-half;  kq2/kq3: layer1 Whh1 k-half
//   kq3 folds x[t] into its layer0 partial and stages x[t+1]
//   kq0 finalizes layer0; kq1 finalizes layer1 + FC
// Sync per step: producers (kq0+kq1) bar.sync -> red.release ->
// ALL threads pure-spin on group flag -> each warp issues its own cp.async
// (no wake-up syncthreads, no nanosleep).
// ---------------------------------------------------------------------------

#define S_LEN  4096
#define BATCH  64
#define IN0    14
#define HID    256
#define NB     128
#define NT     512
#define NGRP   8
#define GCTAS  16
#define JL     16
#define BG     8
#define HBUF   (HID*BG)

// ---- global scratch --------------------------------------------------------
__device__ float    g_h0x[NGRP][2][HBUF];   // [(kp*8+b)*2 + (k&1)]
__device__ float    g_h1x[NGRP][2][HBUF];
__device__ unsigned g_barG[NGRP * 32];

// ---- packed fp32x2 helpers -------------------------------------------------
__device__ __forceinline__ unsigned long long pack2(float x, float y) {
    unsigned long long r;
    asm("mov.b64 %0, {%1,%2};" : "=l"(r) : "f"(x), "f"(y));
    return r;
}
__device__ __forceinline__ void unpack2(unsigned long long v, float& x, float& y) {
    asm("mov.b64 {%0,%1}, %2;" : "=f"(x), "=f"(y) : "l"(v));
}
__device__ __forceinline__ unsigned long long ffma2(unsigned long long a,
                                                    unsigned long long b,
                                                    unsigned long long c) {
    unsigned long long d;
    asm("fma.rn.f32x2 %0, %1, %2, %3;" : "=l"(d) : "l"(a), "l"(b), "l"(c));
    return d;
}
__device__ __forceinline__ float sum2(unsigned long long v) {
    float lo, hi; unpack2(v, lo, hi); return lo + hi;
}

// ---- activations -----------------------------------------------------------
__device__ __forceinline__ float sigmoidf_(float v) {
    return 1.0f / (1.0f + __expf(-v));
}
__device__ __forceinline__ float tanh_acc(float v) {
    float a = fabsf(v);
    float e = __expf(-2.0f * a);
    float r = __fdividef(1.0f - e, 1.0f + e);
    return v < 0.0f ? -r : r;
}

// ---- sync primitives -------------------------------------------------------
__device__ __forceinline__ void red_rel_add(unsigned* p) {
    asm volatile("red.release.gpu.global.add.u32 [%0], %1;" :: "l"(p), "r"(1u) : "memory");
}
__device__ __forceinline__ unsigned ld_acq(const unsigned* p) {
    unsigned v;
    asm volatile("ld.acquire.gpu.global.u32 %0, [%1];" : "=r"(v) : "l"(p) : "memory");
    return v;
}
__device__ __forceinline__ void cp16(uint32_t dst, const void* src) {
    asm volatile("cp.async.cg.shared.global [%0], [%1], 16;" :: "r"(dst), "l"(src));
}
__device__ __forceinline__ void mbar_init(uint32_t a, uint32_t cnt) {
    asm volatile("mbarrier.init.shared.b64 [%0], %1;" :: "r"(a), "r"(cnt) : "memory");
}
__device__ __forceinline__ void cp_arrive_noinc(uint32_t a) {
    asm volatile("cp.async.mbarrier.arrive.noinc.shared.b64 [%0];" :: "r"(a) : "memory");
}
__device__ __forceinline__ void mbar_wait_parity(uint32_t addr, uint32_t parity) {
    asm volatile(
        "{\n\t.reg .pred P;\n"
        "MW_%=:\n\t"
        "mbarrier.try_wait.parity.shared::cta.b64 P, [%0], %1;\n\t"
        "@!P bra MW_%=;\n\t}"
        :: "r"(addr), "r"(parity) : "memory");
}
__device__ __forceinline__ float warp_reduce(float p) {
    #pragma unroll
    for (int o = 16; o > 0; o >>= 1) p += __shfl_xor_sync(0xffffffffu, p, o);
    return p;
}

// ---- smem layout (bytes) ---------------------------------------------------
#define SH_W0    0          // 65536  Whh0   ull slot (kp*16+jl)*4+gate
#define SH_WI1   65536      // 65536  Wih1
#define SH_WH1   131072     // 65536  Whh1
#define SH_WI0   196608     // 3584   float4 wi0[16][14]
#define SH_H0    200192     // 8192   ull[kp128][b8]
#define SH_H1    208384     // 8192
#define SH_PL0   216576     // 6144   float4[3][128]
#define SH_PL1   222720     // 6144   float4[3][128]
#define SH_X     228864     // 896    float[2][112]
#define SH_RED   229760     // 32
#define SH_MBAR  229792     // 16
#define SMEM_TOTAL 229808

extern "C" __global__ void __launch_bounds__(NT, 1)
lstm_fused(const float* __restrict__ x,   const float* __restrict__ c0,
           const float* __restrict__ Wih0, const float* __restrict__ Whh0,
           const float* __restrict__ bih0, const float* __restrict__ bhh0,
           const float* __restrict__ Wih1, const float* __restrict__ Whh1,
           const float* __restrict__ bih1, const float* __restrict__ bhh1,
           const float* __restrict__ Wfc,  const float* __restrict__ bfc,
           float* __restrict__ out)
{
    extern __shared__ char smem[];
    unsigned long long* w0u    = (unsigned long long*)(smem + SH_W0);
    unsigned long long* wi1u   = (unsigned long long*)(smem + SH_WI1);
    unsigned long long* wh1u   = (unsigned long long*)(smem + SH_WH1);
    float4*             wi0    = (float4*)(smem + SH_WI0);
    unsigned long long* sh_h0u = (unsigned long long*)(smem + SH_H0);
    unsigned long long* sh_h1u = (unsigned long long*)(smem + SH_H1);
    float*              sh_h1f = (float*)(smem + SH_H1);
    float4*             pl0    = (float4*)(smem + SH_PL0);
    float4*             pl1    = (float4*)(smem + SH_PL1);
    float*              shx    = (float*)(smem + SH_X);
    float*              red4   = (float*)(smem + SH_RED);

    const uint32_t smem_h0 = (uint32_t)__cvta_generic_to_shared(smem + SH_H0);
    const uint32_t smem_h1 = (uint32_t)__cvta_generic_to_shared(smem + SH_H1);
    const uint32_t mb0     = (uint32_t)__cvta_generic_to_shared(smem + SH_MBAR);
    const uint32_t mb1     = mb0 + 8;

    const int tid = threadIdx.x;
    const int bid = blockIdx.x;
    const int gid = bid >> 4;
    const int ci  = bid & 15;
    const int kq  = tid >> 7;           // 0..3
    const int f   = tid & 127;
    const int jl  = f >> 3;
    const int b   = f & 7;
    const int jglob = ci * JL + jl;

    if (tid == 0) { mbar_init(mb0, NT); mbar_init(mb1, NT); }

    // ---- preload weight slices --------------------------------------------
    for (int e = tid; e < 128 * 16 * 4; e += NT) {
        int kp = e & 127;
        int r  = e >> 7;
        int wjl = r >> 2, gsel = r & 3;
        int row = (gsel * HID + ci * JL + wjl) * HID + 2 * kp;
        int slot = (kp * 16 + wjl) * 4 + gsel;
        w0u [slot] = pack2(Whh0[row], Whh0[row + 1]);
        wi1u[slot] = pack2(Wih1[row], Wih1[row + 1]);
        wh1u[slot] = pack2(Whh1[row], Whh1[row + 1]);
    }
    for (int e = tid; e < JL * IN0; e += NT) {
        int wjl = e / IN0, d = e % IN0;
        int jg = ci * JL + wjl;
        wi0[wjl * IN0 + d] = make_float4(
            Wih0[(0*HID + jg)*IN0 + d], Wih0[(1*HID + jg)*IN0 + d],
            Wih0[(2*HID + jg)*IN0 + d], Wih0[(3*HID + jg)*IN0 + d]);
    }

    // ---- per-role state ----------------------------------------------------
    const int bglob = gid * BG + b;
    float bs0 = 0.f, bs1 = 0.f, bs2 = 0.f, bs3 = 0.f, cst = 0.f;
    if (kq == 0) {
        bs0 = bih0[0*HID+jglob] + bhh0[0*HID+jglob];
        bs1 = bih0[1*HID+jglob] + bhh0[1*HID+jglob];
        bs2 = bih0[2*HID+jglob] + bhh0[2*HID+jglob];
        bs3 = bih0[3*HID+jglob] + bhh0[3*HID+jglob];
        cst = c0[bglob*HID + jglob];
    } else if (kq == 1) {
        bs0 = bih1[0*HID+jglob] + bhh1[0*HID+jglob];
        bs1 = bih1[1*HID+jglob] + bhh1[1*HID+jglob];
        bs2 = bih1[2*HID+jglob] + bhh1[2*HID+jglob];
        bs3 = bih1[3*HID+jglob] + bhh1[3*HID+jglob];
        cst = c0[(BATCH + bglob)*HID + jglob];
    }
    const float wfcA = Wfc[f];
    const float wfcB = Wfc[f + 128];
    const float bfc0 = bfc[0];

    for (int e = tid; e < BG*IN0; e += NT)
        shx[e] = x[(size_t)gid*BG*IN0 + e];
    __syncthreads();

    unsigned* bar = &g_barG[gid * 32];
    const int storeIdx = ((ci*8 + (jl>>1))*8 + b)*2 + (jl&1);

    // ---- prologue: prime cp.async for t=0 (parity 0) -----------------------
    {
        const float4* s0 = (const float4*)g_h0x[gid][0];
        const float4* s1 = (const float4*)g_h1x[gid][0];
        cp16(smem_h0 + tid*16, s0 + tid);
        cp_arrive_noinc(mb0);
        cp16(smem_h1 + tid*16, s1 + tid);
        cp_arrive_noinc(mb1);
    }

    for (int t = 0; t <= S_LEN; ++t) {
        const uint32_t par = (uint32_t)(t & 1);

        mbar_wait_parity(mb0, par);

        // ---- layer0 k-quarter (all roles) ----------------------------------
        unsigned long long a0=0,a1=0,a2=0,a3=0;
        if (t < S_LEN) {
            const unsigned long long* hp = sh_h0u + kq*32*8 + b;
            const unsigned long long* wq = w0u + kq*32*64 + jl*4;
            #pragma unroll 8
            for (int kp = 0; kp < 32; ++kp) {
                unsigned long long hv = hp[kp*8];
                const unsigned long long* w = wq + kp*64;
                ulonglong2 wA = *(const ulonglong2*)(w);
                ulonglong2 wB = *(const ulonglong2*)(w + 2);
                a0 = ffma2(hv, wA.x, a0); a1 = ffma2(hv, wA.y, a1);
                a2 = ffma2(hv, wB.x, a2); a3 = ffma2(hv, wB.y, a3);
            }
        }
        float l0x = sum2(a0), l0y = sum2(a1), l0z = sum2(a2), l0w = sum2(a3);

        // kq3: fold x[t] contribution; stage x[t+1] (ordered by combine sync)
        if (kq == 3) {
            if (t < S_LEN) {
                const float*  xr = shx + (t & 1)*(BG*IN0) + b*IN0;
                const float4* wi = wi0 + jl*IN0;
                #pragma unroll
                for (int d = 0; d < IN0; ++d) {
                    float xv = xr[d]; float4 w = wi[d];
                    l0x = fmaf(xv, w.x, l0x); l0y = fmaf(xv, w.y, l0y);
                    l0z = fmaf(xv, w.z, l0z); l0w = fmaf(xv, w.w, l0w);
                }
            }
            if (t + 1 < S_LEN && f < BG*IN0)
                shx[((t+1)&1)*(BG*IN0) + f] =
                    x[((size_t)(t+1)*BATCH + gid*BG)*IN0 + f];
        }
        if (kq != 0) pl0[(kq-1)*128 + f] = make_float4(l0x, l0y, l0z, l0w);

        // ---- layer1 half-GEMMs ---------------------------------------------
        unsigned long long e0=0,e1=0,e2=0,e3=0;
        if (kq < 2) {
            if (t >= 1) {                       // Wih1 x h0[t-1], half kq
                const unsigned long long* hp = sh_h0u + kq*64*8 + b;
                const unsigned long long* wq = wi1u + kq*64*64 + jl*4;
                #pragma unroll 8
                for (int kp = 0; kp < 64; ++kp) {
                    unsigned long long hv = hp[kp*8];
                    const unsigned long long* w = wq + kp*64;
                    ulonglong2 wA = *(const ulonglong2*)(w);
                    ulonglong2 wB = *(const ulonglong2*)(w + 2);
                    e0 = ffma2(hv, wA.x, e0); e1 = ffma2(hv, wA.y, e1);
                    e2 = ffma2(hv, wB.x, e2); e3 = ffma2(hv, wB.y, e3);
                }
            }
            if (kq == 0)
                pl1[f] = make_float4(sum2(e0), sum2(e1), sum2(e2), sum2(e3));
            else if (t >= 2) {
                // ---- fused FC for out[t-2]: reads sh_h1 (pre-combine, safe:
                // sh_h1 is only overwritten after every thread passes the
                // post-spin cp.async, which is after the combine sync) -------
                mbar_wait_parity(mb1, par);
                if (ci < BG) {
                    int j1 = f, j2 = f + 128;
                    float vA = sh_h1f[(j1>>1)*16 + ci*2 + (j1&1)];
                    float vB = sh_h1f[(j2>>1)*16 + ci*2 + (j2&1)];
                    float p = fmaxf(vA, 0.f)*wfcA + fmaxf(vB, 0.f)*wfcB;
                    p = warp_reduce(p);
                    if ((f & 31) == 0) red4[f >> 5] = p;
                    asm volatile("bar.sync 2, 128;" ::: "memory");
                    if (f == 0)
                        out[(size_t)(t-2)*BATCH + gid*BG + ci] =
                            red4[0]+red4[1]+red4[2]+red4[3] + bfc0;
                }
            }
        } else {
            mbar_wait_parity(mb1, par);
            if (t >= 1) {                       // Whh1 x h1[t-2], half kq-2
                const int kh = kq - 2;
                const unsigned long long* hp = sh_h1u + kh*64*8 + b;
                const unsigned long long* wq = wh1u + kh*64*64 + jl*4;
                #pragma unroll 8
                for (int kp = 0; kp < 64; ++kp) {
                    unsigned long long hv = hp[kp*8];
                    const unsigned long long* w = wq + kp*64;
                    ulonglong2 wA = *(const ulonglong2*)(w);
                    ulonglong2 wB = *(const ulonglong2*)(w + 2);
                    e0 = ffma2(hv, wA.x, e0); e1 = ffma2(hv, wA.y, e1);
                    e2 = ffma2(hv, wB.x, e2); e3 = ffma2(hv, wB.y, e3);
                }
            }
            pl1[(kq-1)*128 + f] = make_float4(sum2(e0), sum2(e1), sum2(e2), sum2(e3));
        }

        // ---- combine sync: also marks "all reads of sh_h0/sh_h1 done" ------
        __syncthreads();

        if (kq == 0) {
            if (t < S_LEN) {                    // finalize layer0 -> h0[t]
                float4 p1 = pl0[f], p2 = pl0[128+f], p3 = pl0[256+f];
                float gi = l0x + p1.x + p2.x + p3.x + bs0;
                float gf = l0y + p1.y + p2.y + p3.y + bs1;
                float gg = l0z + p1.z + p2.z + p3.z + bs2;
                float go = l0w + p1.w + p2.w + p3.w + bs3;
                gi = sigmoidf_(gi); gf = sigmoidf_(gf);
                gg = tanh_acc(gg);  go = sigmoidf_(go);
                cst = gf*cst + gi*gg;
                float h = go * tanh_acc(cst);
                g_h0x[gid][(t+1)&1][storeIdx] = h;
            }
        } else if (kq == 1) {
            if (t >= 1) {                       // finalize layer1 -> h1[t-1]
                float4 p1 = pl1[f], p2 = pl1[128+f], p3 = pl1[256+f];
                float gi = sum2(e0) + p1.x + p2.x + p3.x + bs0;
                float gf = sum2(e1) + p1.y + p2.y + p3.y + bs1;
                float gg = sum2(e2) + p1.z + p2.z + p3.z + bs2;
                float go = sum2(e3) + p1.w + p2.w + p3.w + bs3;
                gi = sigmoidf_(gi); gf = sigmoidf_(gf);
                gg = tanh_acc(gg);  go = sigmoidf_(go);
                cst = gf*cst + gi*gg;
                float h = go * tanh_acc(cst);
                g_h1x[gid][(t+1)&1][storeIdx] = h;
            }
        }

        if (t < S_LEN) {
            // ---- producer barrier + release (kq0+kq1 = threads 0..255) -----
            if (kq < 2) {
                asm volatile("bar.sync 3, 256;" ::: "memory");
                if (tid == 0) red_rel_add(bar);
            }
            // ---- all threads: pure spin, then issue own cp.async slice -----
            const unsigned target = (unsigned)GCTAS * (unsigned)(t + 1);
            while (ld_acq(bar) < target) { }
            const int npar = (t + 1) & 1;
            const float4* s0 = (const float4*)g_h0x[gid][npar];
            const float4* s1 = (const float4*)g_h1x[gid][npar];
            cp16(smem_h0 + tid*16, s0 + tid);
            cp_arrive_noinc(mb0);
            cp16(smem_h1 + tid*16, s1 + tid);
            cp_arrive_noinc(mb1);
        }
    }

    // ---- final FC row 4095: h1[4095] in g_h1x[gid][1] ----------------------
    if (kq == 1 && ci < BG) {
        int j1 = f, j2 = f + 128;
        float vA = __ldcg(&g_h1x[gid][1][(j1>>1)*16 + ci*2 + (j1&1)]);
        float vB = __ldcg(&g_h1x[gid][1][(j2>>1)*16 + ci*2 + (j2&1)]);
        float p = fmaxf(vA, 0.f)*wfcA + fmaxf(vB, 0.f)*wfcB;
        p = warp_reduce(p);
        if ((f & 31) == 0) red4[f >> 5] = p;
        asm volatile("bar.sync 2, 128;" ::: "memory");
        if (f == 0)
            out[(size_t)(S_LEN-1)*BATCH + gid*BG + ci] =
                red4[0]+red4[1]+red4[2]+red4[3] + bfc0;
    }
}

// ---------------------------------------------------------------------------
// Init: reset group barriers; scatter h0 init into exchange buffers.
// ---------------------------------------------------------------------------
extern "C" __global__ void lstm_init(const float* __restrict__ h0)
{
    int i = blockIdx.x * blockDim.x + threadIdx.x;
    if (i < NGRP * 32) g_barG[i] = 0u;
    for (int idx = i; idx < 2 * NGRP * HBUF; idx += gridDim.x * blockDim.x) {
        int l = idx >> 14;
        int rest = idx & 16383;
        int g = rest >> 11;
        int q = rest & 2047;
        int kp = q >> 4;
        int b  = (q >> 1) & 7;
        int par = q & 1;
        int k = kp*2 + par;
        float v = h0[(l*BATCH + g*BG + b)*HID + k];
        if (l == 0) g_h0x[g][0][q] = v;
        else        g_h1x[g][1][q] = v;
    }
}

// ---------------------------------------------------------------------------
extern "C" void kernel_launch(void* const* d_in, const int* in_sizes, int n_in,
                              void* d_out, int out_size)
{
    const float* x    = (const float*)d_in[0];
    const float* h0   = (const float*)d_in[1];
    const float* c0   = (const float*)d_in[2];
    const float* Wih0 = (const float*)d_in[3];
    const float* Whh0 = (const float*)d_in[4];
    const float* bih0 = (const float*)d_in[5];
    const float* bhh0 = (const float*)d_in[6];
    const float* Wih1 = (const float*)d_in[7];
    const float* Whh1 = (const float*)d_in[8];
    const float* bih1 = (const float*)d_in[9];
    const float* bhh1 = (const float*)d_in[10];
    const float* Wfc  = (const float*)d_in[11];
    const float* bfc  = (const float*)d_in[12];
    float* out = (float*)d_out;

    cudaFuncSetAttribute(lstm_fused, cudaFuncAttributeMaxDynamicSharedMemorySize, SMEM_TOTAL);

    lstm_init<<<64, 256>>>(h0);
    lstm_fused<<<NB, NT, SMEM_TOTAL>>>(x, c0, Wih0, Whh0, bih0, bhh0,
                                       Wih1, Whh1, bih1, bhh1, Wfc, bfc, out);
}

// round 8
// speedup vs baseline: 1.5960x; 1.0078x over previous
#include <cuda_runtime.h>
#include <cstdint>

// ---------------------------------------------------------------------------
// Fused 2-layer LSTM, S=4096, B=64, I=14, H=256, O=1 (gate order i,f,g,o)
//
// 8 batch groups x 16 CTAs; each CTA: weight replica slice in smem,
// 16 hidden units x 8 batch elems, BOTH layers. NT=512.
// Thread = (kq, jl, b):
//   all kq: layer0 k-quarter (32 kp)
//   kq0/kq1: layer1 Wih1 k-half;  kq2/kq3: layer1 Whh1 k-half
//   kq3 folds x[t] into its layer0 partial and stages x[t+1]
//   kq0 finalizes layer0; kq1 finalizes layer1 + FC
// Sync per step: producers (kq0+kq1) bar.sync -> red.release ->
// ALL threads pure-spin on group flag -> each warp issues its own cp.async
// (no wake-up syncthreads, no nanosleep).
// ---------------------------------------------------------------------------

#define S_LEN  4096
#define BATCH  64
#define IN0    14
#define HID    256
#define NB     128
#define NT     512
#define NGRP   8
#define GCTAS  16
#define JL     16
#define BG     8
#define HBUF   (HID*BG)

// ---- global scratch --------------------------------------------------------
__device__ float    g_h0x[NGRP][2][HBUF];   // [(kp*8+b)*2 + (k&1)]
__device__ float    g_h1x[NGRP][2][HBUF];
__device__ unsigned g_barG[NGRP * 32];

// ---- packed fp32x2 helpers -------------------------------------------------
__device__ __forceinline__ unsigned long long pack2(float x, float y) {
    unsigned long long r;
    asm("mov.b64 %0, {%1,%2};" : "=l"(r) : "f"(x), "f"(y));
    return r;
}
__device__ __forceinline__ void unpack2(unsigned long long v, float& x, float& y) {
    asm("mov.b64 {%0,%1}, %2;" : "=f"(x), "=f"(y) : "l"(v));
}
__device__ __forceinline__ unsigned long long ffma2(unsigned long long a,
                                                    unsigned long long b,
                                                    unsigned long long c) {
    unsigned long long d;
    asm("fma.rn.f32x2 %0, %1, %2, %3;" : "=l"(d) : "l"(a), "l"(b), "l"(c));
    return d;
}
__device__ __forceinline__ float sum2(unsigned long long v) {
    float lo, hi; unpack2(v, lo, hi); return lo + hi;
}

// ---- activations -----------------------------------------------------------
__device__ __forceinline__ float sigmoidf_(float v) {
    return 1.0f / (1.0f + __expf(-v));
}
__device__ __forceinline__ float tanh_acc(float v) {
    float a = fabsf(v);
    float e = __expf(-2.0f * a);
    float r = __fdividef(1.0f - e, 1.0f + e);
    return v < 0.0f ? -r : r;
}

// ---- sync primitives -------------------------------------------------------
__device__ __forceinline__ void red_rel_add(unsigned* p) {
    asm volatile("red.release.gpu.global.add.u32 [%0], %1;" :: "l"(p), "r"(1u) : "memory");
}
__device__ __forceinline__ unsigned ld_acq(const unsigned* p) {
    unsigned v;
    asm volatile("ld.acquire.gpu.global.u32 %0, [%1];" : "=r"(v) : "l"(p) : "memory");
    return v;
}
__device__ __forceinline__ void cp16(uint32_t dst, const void* src) {
    asm volatile("cp.async.cg.shared.global [%0], [%1], 16;" :: "r"(dst), "l"(src));
}
__device__ __forceinline__ void mbar_init(uint32_t a, uint32_t cnt) {
    asm volatile("mbarrier.init.shared.b64 [%0], %1;" :: "r"(a), "r"(cnt) : "memory");
}
__device__ __forceinline__ void cp_arrive_noinc(uint32_t a) {
    asm volatile("cp.async.mbarrier.arrive.noinc.shared.b64 [%0];" :: "r"(a) : "memory");
}
__device__ __forceinline__ void mbar_wait_parity(uint32_t addr, uint32_t parity) {
    asm volatile(
        "{\n\t.reg .pred P;\n"
        "MW_%=:\n\t"
        "mbarrier.try_wait.parity.shared::cta.b64 P, [%0], %1;\n\t"
        "@!P bra MW_%=;\n\t}"
        :: "r"(addr), "r"(parity) : "memory");
}
__device__ __forceinline__ float warp_reduce(float p) {
    #pragma unroll
    for (int o = 16; o > 0; o >>= 1) p += __shfl_xor_sync(0xffffffffu, p, o);
    return p;
}

// ---- smem layout (bytes) ---------------------------------------------------
#define SH_W0    0          // 65536  Whh0   ull slot (kp*16+jl)*4+gate
#define SH_WI1   65536      // 65536  Wih1
#define SH_WH1   131072     // 65536  Whh1
#define SH_WI0   196608     // 3584   float4 wi0[16][14]
#define SH_H0    200192     // 8192   ull[kp128][b8]
#define SH_H1    208384     // 8192
#define SH_PL0   216576     // 6144   float4[3][128]
#define SH_PL1   222720     // 6144   float4[3][128]
#define SH_X     228864     // 896    float[2][112]
#define SH_RED   229760     // 32
#define SH_MBAR  229792     // 16
#define SMEM_TOTAL 229808

extern "C" __global__ void __launch_bounds__(NT, 1)
lstm_fused(const float* __restrict__ x,   const float* __restrict__ c0,
           const float* __restrict__ Wih0, const float* __restrict__ Whh0,
           const float* __restrict__ bih0, const float* __restrict__ bhh0,
           const float* __restrict__ Wih1, const float* __restrict__ Whh1,
           const float* __restrict__ bih1, const float* __restrict__ bhh1,
           const float* __restrict__ Wfc,  const float* __restrict__ bfc,
           float* __restrict__ out)
{
    extern __shared__ char smem[];
    unsigned long long* w0u    = (unsigned long long*)(smem + SH_W0);
    unsigned long long* wi1u   = (unsigned long long*)(smem + SH_WI1);
    unsigned long long* wh1u   = (unsigned long long*)(smem + SH_WH1);
    float4*             wi0    = (float4*)(smem + SH_WI0);
    unsigned long long* sh_h0u = (unsigned long long*)(smem + SH_H0);
    unsigned long long* sh_h1u = (unsigned long long*)(smem + SH_H1);
    float*              sh_h1f = (float*)(smem + SH_H1);
    float4*             pl0    = (float4*)(smem + SH_PL0);
    float4*             pl1    = (float4*)(smem + SH_PL1);
    float*              shx    = (float*)(smem + SH_X);
    float*              red4   = (float*)(smem + SH_RED);

    const uint32_t smem_h0 = (uint32_t)__cvta_generic_to_shared(smem + SH_H0);
    const uint32_t smem_h1 = (uint32_t)__cvta_generic_to_shared(smem + SH_H1);
    const uint32_t mb0     = (uint32_t)__cvta_generic_to_shared(smem + SH_MBAR);
    const uint32_t mb1     = mb0 + 8;

    const int tid = threadIdx.x;
    const int bid = blockIdx.x;
    const int gid = bid >> 4;
    const int ci  = bid & 15;
    const int kq  = tid >> 7;           // 0..3
    const int f   = tid & 127;
    const int jl  = f >> 3;
    const int b   = f & 7;
    const int jglob = ci * JL + jl;

    if (tid == 0) { mbar_init(mb0, NT); mbar_init(mb1, NT); }

    // ---- preload weight slices --------------------------------------------
    for (int e = tid; e < 128 * 16 * 4; e += NT) {
        int kp = e & 127;
        int r  = e >> 7;
        int wjl = r >> 2, gsel = r & 3;
        int row = (gsel * HID + ci * JL + wjl) * HID + 2 * kp;
        int slot = (kp * 16 + wjl) * 4 + gsel;
        w0u [slot] = pack2(Whh0[row], Whh0[row + 1]);
        wi1u[slot] = pack2(Wih1[row], Wih1[row + 1]);
        wh1u[slot] = pack2(Whh1[row], Whh1[row + 1]);
    }
    for (int e = tid; e < JL * IN0; e += NT) {
        int wjl = e / IN0, d = e % IN0;
        int jg = ci * JL + wjl;
        wi0[wjl * IN0 + d] = make_float4(
            Wih0[(0*HID + jg)*IN0 + d], Wih0[(1*HID + jg)*IN0 + d],
            Wih0[(2*HID + jg)*IN0 + d], Wih0[(3*HID + jg)*IN0 + d]);
    }

    // ---- per-role state ----------------------------------------------------
    const int bglob = gid * BG + b;
    float bs0 = 0.f, bs1 = 0.f, bs2 = 0.f, bs3 = 0.f, cst = 0.f;
    if (kq == 0) {
        bs0 = bih0[0*HID+jglob] + bhh0[0*HID+jglob];
        bs1 = bih0[1*HID+jglob] + bhh0[1*HID+jglob];
        bs2 = bih0[2*HID+jglob] + bhh0[2*HID+jglob];
        bs3 = bih0[3*HID+jglob] + bhh0[3*HID+jglob];
        cst = c0[bglob*HID + jglob];
    } else if (kq == 1) {
        bs0 = bih1[0*HID+jglob] + bhh1[0*HID+jglob];
        bs1 = bih1[1*HID+jglob] + bhh1[1*HID+jglob];
        bs2 = bih1[2*HID+jglob] + bhh1[2*HID+jglob];
        bs3 = bih1[3*HID+jglob] + bhh1[3*HID+jglob];
        cst = c0[(BATCH + bglob)*HID + jglob];
    }
    const float wfcA = Wfc[f];
    const float wfcB = Wfc[f + 128];
    const float bfc0 = bfc[0];

    for (int e = tid; e < BG*IN0; e += NT)
        shx[e] = x[(size_t)gid*BG*IN0 + e];
    __syncthreads();

    unsigned* bar = &g_barG[gid * 32];
    const int storeIdx = ((ci*8 + (jl>>1))*8 + b)*2 + (jl&1);

    // ---- prologue: prime cp.async for t=0 (parity 0) -----------------------
    {
        const float4* s0 = (const float4*)g_h0x[gid][0];
        const float4* s1 = (const float4*)g_h1x[gid][0];
        cp16(smem_h0 + tid*16, s0 + tid);
        cp_arrive_noinc(mb0);
        cp16(smem_h1 + tid*16, s1 + tid);
        cp_arrive_noinc(mb1);
    }

    for (int t = 0; t <= S_LEN; ++t) {
        const uint32_t par = (uint32_t)(t & 1);

        mbar_wait_parity(mb0, par);

        // ---- layer0 k-quarter (all roles) ----------------------------------
        unsigned long long a0=0,a1=0,a2=0,a3=0;
        if (t < S_LEN) {
            const unsigned long long* hp = sh_h0u + kq*32*8 + b;
            const unsigned long long* wq = w0u + kq*32*64 + jl*4;
            #pragma unroll 8
            for (int kp = 0; kp < 32; ++kp) {
                unsigned long long hv = hp[kp*8];
                const unsigned long long* w = wq + kp*64;
                ulonglong2 wA = *(const ulonglong2*)(w);
                ulonglong2 wB = *(const ulonglong2*)(w + 2);
                a0 = ffma2(hv, wA.x, a0); a1 = ffma2(hv, wA.y, a1);
                a2 = ffma2(hv, wB.x, a2); a3 = ffma2(hv, wB.y, a3);
            }
        }
        float l0x = sum2(a0), l0y = sum2(a1), l0z = sum2(a2), l0w = sum2(a3);

        // kq3: fold x[t] contribution; stage x[t+1] (ordered by combine sync)
        if (kq == 3) {
            if (t < S_LEN) {
                const float*  xr = shx + (t & 1)*(BG*IN0) + b*IN0;
                const float4* wi = wi0 + jl*IN0;
                #pragma unroll
                for (int d = 0; d < IN0; ++d) {
                    float xv = xr[d]; float4 w = wi[d];
                    l0x = fmaf(xv, w.x, l0x); l0y = fmaf(xv, w.y, l0y);
                    l0z = fmaf(xv, w.z, l0z); l0w = fmaf(xv, w.w, l0w);
                }
            }
            if (t + 1 < S_LEN && f < BG*IN0)
                shx[((t+1)&1)*(BG*IN0) + f] =
                    x[((size_t)(t+1)*BATCH + gid*BG)*IN0 + f];
        }
        if (kq != 0) pl0[(kq-1)*128 + f] = make_float4(l0x, l0y, l0z, l0w);

        // ---- layer1 half-GEMMs ---------------------------------------------
        unsigned long long e0=0,e1=0,e2=0,e3=0;
        if (kq < 2) {
            if (t >= 1) {                       // Wih1 x h0[t-1], half kq
                const unsigned long long* hp = sh_h0u + kq*64*8 + b;
                const unsigned long long* wq = wi1u + kq*64*64 + jl*4;
                #pragma unroll 8
                for (int kp = 0; kp < 64; ++kp) {
                    unsigned long long hv = hp[kp*8];
                    const unsigned long long* w = wq + kp*64;
                    ulonglong2 wA = *(const ulonglong2*)(w);
                    ulonglong2 wB = *(const ulonglong2*)(w + 2);
                    e0 = ffma2(hv, wA.x, e0); e1 = ffma2(hv, wA.y, e1);
                    e2 = ffma2(hv, wB.x, e2); e3 = ffma2(hv, wB.y, e3);
                }
            }
            if (kq == 0)
                pl1[f] = make_float4(sum2(e0), sum2(e1), sum2(e2), sum2(e3));
            else if (t >= 2) {
                // ---- fused FC for out[t-2]: reads sh_h1 (pre-combine, safe:
                // sh_h1 is only overwritten after every thread passes the
                // post-spin cp.async, which is after the combine sync) -------
                mbar_wait_parity(mb1, par);
                if (ci < BG) {
                    int j1 = f, j2 = f + 128;
                    float vA = sh_h1f[(j1>>1)*16 + ci*2 + (j1&1)];
                    float vB = sh_h1f[(j2>>1)*16 + ci*2 + (j2&1)];
                    float p = fmaxf(vA, 0.f)*wfcA + fmaxf(vB, 0.f)*wfcB;
                    p = warp_reduce(p);
                    if ((f & 31) == 0) red4[f >> 5] = p;
                    asm volatile("bar.sync 2, 128;" ::: "memory");
                    if (f == 0)
                        out[(size_t)(t-2)*BATCH + gid*BG + ci] =
                            red4[0]+red4[1]+red4[2]+red4[3] + bfc0;
                }
            }
        } else {
            mbar_wait_parity(mb1, par);
            if (t >= 1) {                       // Whh1 x h1[t-2], half kq-2
                const int kh = kq - 2;
                const unsigned long long* hp = sh_h1u + kh*64*8 + b;
                const unsigned long long* wq = wh1u + kh*64*64 + jl*4;
                #pragma unroll 8
                for (int kp = 0; kp < 64; ++kp) {
                    unsigned long long hv = hp[kp*8];
                    const unsigned long long* w = wq + kp*64;
                    ulonglong2 wA = *(const ulonglong2*)(w);
                    ulonglong2 wB = *(const ulonglong2*)(w + 2);
                    e0 = ffma2(hv, wA.x, e0); e1 = ffma2(hv, wA.y, e1);
                    e2 = ffma2(hv, wB.x, e2); e3 = ffma2(hv, wB.y, e3);
                }
            }
            pl1[(kq-1)*128 + f] = make_float4(sum2(e0), sum2(e1), sum2(e2), sum2(e3));
        }

        // ---- combine sync: also marks "all reads of sh_h0/sh_h1 done" ------
        __syncthreads();

        if (kq == 0) {
            if (t < S_LEN) {                    // finalize layer0 -> h0[t]
                float4 p1 = pl0[f], p2 = pl0[128+f], p3 = pl0[256+f];
                float gi = l0x + p1.x + p2.x + p3.x + bs0;
                float gf = l0y + p1.y + p2.y + p3.y + bs1;
                float gg = l0z + p1.z + p2.z + p3.z + bs2;
                float go = l0w + p1.w + p2.w + p3.w + bs3;
                gi = sigmoidf_(gi); gf = sigmoidf_(gf);
                gg = tanh_acc(gg);  go = sigmoidf_(go);
                cst = gf*cst + gi*gg;
                float h = go * tanh_acc(cst);
                g_h0x[gid][(t+1)&1][storeIdx] = h;
            }
        } else if (kq == 1) {
            if (t >= 1) {                       // finalize layer1 -> h1[t-1]
                float4 p1 = pl1[f], p2 = pl1[128+f], p3 = pl1[256+f];
                float gi = sum2(e0) + p1.x + p2.x + p3.x + bs0;
                float gf = sum2(e1) + p1.y + p2.y + p3.y + bs1;
                float gg = sum2(e2) + p1.z + p2.z + p3.z + bs2;
                float go = sum2(e3) + p1.w + p2.w + p3.w + bs3;
                gi = sigmoidf_(gi); gf = sigmoidf_(gf);
                gg = tanh_acc(gg);  go = sigmoidf_(go);
                cst = gf*cst + gi*gg;
                float h = go * tanh_acc(cst);
                g_h1x[gid][(t+1)&1][storeIdx] = h;
            }
        }

        if (t < S_LEN) {
            // ---- producer barrier + release (kq0+kq1 = threads 0..255) -----
            if (kq < 2) {
                asm volatile("bar.sync 3, 256;" ::: "memory");
                if (tid == 0) red_rel_add(bar);
            }
            // ---- all threads: pure spin, then issue own cp.async slice -----
            const unsigned target = (unsigned)GCTAS * (unsigned)(t + 1);
            while (ld_acq(bar) < target) { }
            const int npar = (t + 1) & 1;
            const float4* s0 = (const float4*)g_h0x[gid][npar];
            const float4* s1 = (const float4*)g_h1x[gid][npar];
            cp16(smem_h0 + tid*16, s0 + tid);
            cp_arrive_noinc(mb0);
            cp16(smem_h1 + tid*16, s1 + tid);
            cp_arrive_noinc(mb1);
        }
    }

    // ---- final FC row 4095: h1[4095] in g_h1x[gid][1] ----------------------
    if (kq == 1 && ci < BG) {
        int j1 = f, j2 = f + 128;
        float vA = __ldcg(&g_h1x[gid][1][(j1>>1)*16 + ci*2 + (j1&1)]);
        float vB = __ldcg(&g_h1x[gid][1][(j2>>1)*16 + ci*2 + (j2&1)]);
        float p = fmaxf(vA, 0.f)*wfcA + fmaxf(vB, 0.f)*wfcB;
        p = warp_reduce(p);
        if ((f & 31) == 0) red4[f >> 5] = p;
        asm volatile("bar.sync 2, 128;" ::: "memory");
        if (f == 0)
            out[(size_t)(S_LEN-1)*BATCH + gid*BG + ci] =
                red4[0]+red4[1]+red4[2]+red4[3] + bfc0;
    }
}

// ---------------------------------------------------------------------------
// Init: reset group barriers; scatter h0 init into exchange buffers.
// ---------------------------------------------------------------------------
extern "C" __global__ void lstm_init(const float* __restrict__ h0)
{
    int i = blockIdx.x * blockDim.x + threadIdx.x;
    if (i < NGRP * 32) g_barG[i] = 0u;
    for (int idx = i; idx < 2 * NGRP * HBUF; idx += gridDim.x * blockDim.x) {
        int l = idx >> 14;
        int rest = idx & 16383;
        int g = rest >> 11;
        int q = rest & 2047;
        int kp = q >> 4;
        int b  = (q >> 1) & 7;
        int par = q & 1;
        int k = kp*2 + par;
        float v = h0[(l*BATCH + g*BG + b)*HID + k];
        if (l == 0) g_h0x[g][0][q] = v;
        else        g_h1x[g][1][q] = v;
    }
}

// ---------------------------------------------------------------------------
extern "C" void kernel_launch(void* const* d_in, const int* in_sizes, int n_in,
                              void* d_out, int out_size)
{
    const float* x    = (const float*)d_in[0];
    const float* h0   = (const float*)d_in[1];
    const float* c0   = (const float*)d_in[2];
    const float* Wih0 = (const float*)d_in[3];
    const float* Whh0 = (const float*)d_in[4];
    const float* bih0 = (const float*)d_in[5];
    const float* bhh0 = (const float*)d_in[6];
    const float* Wih1 = (const float*)d_in[7];
    const float* Whh1 = (const float*)d_in[8];
    const float* bih1 = (const float*)d_in[9];
    const float* bhh1 = (const float*)d_in[10];
    const float* Wfc  = (const float*)d_in[11];
    const float* bfc  = (const float*)d_in[12];
    float* out = (float*)d_out;

    cudaFuncSetAttribute(lstm_fused, cudaFuncAttributeMaxDynamicSharedMemorySize, SMEM_TOTAL);

    lstm_init<<<64, 256>>>(h0);
    lstm_fused<<<NB, NT, SMEM_TOTAL>>>(x, c0, Wih0, Whh0, bih0, bhh0,
                                       Wih1, Whh1, bih1, bhh1, Wfc, bfc, out);
}